// round 9
// baseline (speedup 1.0000x reference)
#include <cuda_runtime.h>
#include <cstdint>

#define BB 8
#define LL 256
#define DD 512
#define HH 512
#define NTOT (LL*BB*LL)          // 524288

// Scratch: transposed projections dl_t[b][h][i], dr_t[b][h][i]
__device__ float g_dlt[BB*HH*LL];
__device__ float g_drt[BB*HH*LL];

// ---------------------------------------------------------------------------
// f32x2 packed-math helpers
// ---------------------------------------------------------------------------
typedef unsigned long long u64;

__device__ __forceinline__ u64 pack2(float lo, float hi) {
    u64 r; asm("mov.b64 %0, {%1, %2};" : "=l"(r) : "f"(lo), "f"(hi)); return r;
}
__device__ __forceinline__ void unpack2(u64 v, float& lo, float& hi) {
    asm("mov.b64 {%0, %1}, %2;" : "=f"(lo), "=f"(hi) : "l"(v));
}
__device__ __forceinline__ void ffma2(u64& d, u64 a, u64 b) {
    asm("fma.rn.f32x2 %0, %1, %2, %0;" : "+l"(d) : "l"(a), "l"(b));
}

// ---------------------------------------------------------------------------
// Kernel 1: fused dual GEMM (round-7 math). Processes batches
// [b_base, b_base + gridDim.z). Block: 64h x 64i tile. 256 threads.
// ---------------------------------------------------------------------------
__global__ __launch_bounds__(256) void dual_gemm_kernel(
    const float* __restrict__ enc,
    const float* __restrict__ Wl,
    const float* __restrict__ Wr,
    int b_base)
{
    const int b  = b_base + blockIdx.z;
    const int h0 = blockIdx.x * 64;
    const int i0 = blockIdx.y * 64;

    __shared__ float se[16][68];   // [k][i] (padded)
    __shared__ float swl[16][64];  // [k][h]
    __shared__ float swr[16][64];

    const int tid = threadIdx.x;
    const int tx  = tid & 15;      // h group (4 h each)
    const int ty  = tid >> 4;      // i group (4 i each)

    u64 accl2[4][2], accr2[4][2];  // [a=i][h-pair]
#pragma unroll
    for (int a = 0; a < 4; a++)
#pragma unroll
        for (int c2 = 0; c2 < 2; c2++) { accl2[a][c2] = 0ull; accr2[a][c2] = 0ull; }

    for (int k0 = 0; k0 < DD; k0 += 16) {
        {
            int kk = tid >> 4;          // 0..15
            int hh = (tid & 15) << 2;   // 0..60
            const float4 vl = *(const float4*)&Wl[(k0 + kk) * HH + h0 + hh];
            const float4 vr = *(const float4*)&Wr[(k0 + kk) * HH + h0 + hh];
            *(float4*)&swl[kk][hh] = vl;
            *(float4*)&swr[kk][hh] = vr;
        }
        {
            int ii = tid >> 2;          // 0..63
            int kk = (tid & 3) << 2;    // 0,4,8,12
            const float4 v = *(const float4*)&enc[(b * LL + i0 + ii) * DD + k0 + kk];
            se[kk + 0][ii] = v.x;
            se[kk + 1][ii] = v.y;
            se[kk + 2][ii] = v.z;
            se[kk + 3][ii] = v.w;
        }
        __syncthreads();

#pragma unroll
        for (int kk = 0; kk < 16; kk++) {
            float ev[4];
            *(float4*)ev = *(const float4*)&se[kk][ty << 2];
            const u64 wl01 = *(const u64*)&swl[kk][tx << 2];
            const u64 wl23 = *(const u64*)&swl[kk][(tx << 2) + 2];
            const u64 wr01 = *(const u64*)&swr[kk][tx << 2];
            const u64 wr23 = *(const u64*)&swr[kk][(tx << 2) + 2];
#pragma unroll
            for (int a = 0; a < 4; a++) {
                const u64 ea = pack2(ev[a], ev[a]);
                ffma2(accl2[a][0], ea, wl01);
                ffma2(accl2[a][1], ea, wl23);
                ffma2(accr2[a][0], ea, wr01);
                ffma2(accr2[a][1], ea, wr23);
            }
        }
        __syncthreads();
    }

#pragma unroll
    for (int c2 = 0; c2 < 2; c2++) {
        float l0[4], l1[4], r0[4], r1[4];
#pragma unroll
        for (int a = 0; a < 4; a++) {
            unpack2(accl2[a][c2], l0[a], l1[a]);
            unpack2(accr2[a][c2], r0[a], r1[a]);
        }
        const int h    = h0 + (tx << 2) + (c2 << 1);
        const int base = (b * HH + h) * LL + i0 + (ty << 2);
        *(float4*)&g_dlt[base]      = make_float4(l0[0], l0[1], l0[2], l0[3]);
        *(float4*)&g_dlt[base + LL] = make_float4(l1[0], l1[1], l1[2], l1[3]);
        *(float4*)&g_drt[base]      = make_float4(r0[0], r0[1], r0[2], r0[3]);
        *(float4*)&g_drt[base + LL] = make_float4(r1[0], r1[1], r1[2], r1[3]);
    }
}

// ---------------------------------------------------------------------------
// Threefry2x32, key (0, 42), partitionable path: counter = (0, m),
// output bits = lane0 ^ lane1.
// ---------------------------------------------------------------------------
__device__ __forceinline__ unsigned threefry_bits_partitionable(unsigned m)
{
    const unsigned k0 = 0u, k1 = 42u;
    const unsigned k2 = 0x1BD11BDAu ^ k0 ^ k1;
    unsigned x0 = 0u + k0;
    unsigned x1 = m  + k1;
#define TF_RND(r) { x0 += x1; x1 = __funnelshift_l(x1, x1, r); x1 ^= x0; }
    TF_RND(13) TF_RND(15) TF_RND(26) TF_RND(6)   x0 += k1; x1 += k2 + 1u;
    TF_RND(17) TF_RND(29) TF_RND(16) TF_RND(24)  x0 += k2; x1 += k0 + 2u;
    TF_RND(13) TF_RND(15) TF_RND(26) TF_RND(6)   x0 += k0; x1 += k1 + 3u;
    TF_RND(17) TF_RND(29) TF_RND(16) TF_RND(24)  x0 += k1; x1 += k2 + 4u;
    TF_RND(13) TF_RND(15) TF_RND(26) TF_RND(6)   x0 += k2; x1 += k0 + 5u;
#undef TF_RND
    return x0 ^ x1;
}

__device__ __forceinline__ float tanh_fast(float x)
{
    float y;
    asm("tanh.approx.f32 %0, %1;" : "=f"(y) : "f"(x));
    return y;
}

// ---------------------------------------------------------------------------
// Kernel 2: biaffine + epilogue (round-7 math). Batches
// [b_base, b_base + gridDim.z). 32i x 16j tile per CTA.
// ---------------------------------------------------------------------------
__global__ __launch_bounds__(256) void biaffine_kernel(
    const float* __restrict__ U,
    const float* __restrict__ logit_bias,
    float* __restrict__ out,
    int b_base)
{
    const int b  = b_base + blockIdx.z;
    const int i0 = blockIdx.y * 32;
    const int j0 = blockIdx.x * 16;

    __shared__ float sl[32][32];   // [h][i]
    __shared__ float sr[32][16];   // [h][j]
    __shared__ float su[32];

    const int tid = threadIdx.x;
    const int tx  = tid & 15;      // j (1 each)
    const int ty  = tid >> 4;      // i group (2 each)

    float acc[2] = {0.f, 0.f};

    for (int h0 = 0; h0 < HH; h0 += 32) {
        {
            int hk  = tid >> 3;             // 0..31
            int col = (tid & 7) << 2;       // 0..28
            *(float4*)&sl[hk][col] = *(const float4*)&g_dlt[(b * HH + h0 + hk) * LL + i0 + col];
        }
        if (tid < 128) {
            int hk  = tid >> 2;             // 0..31
            int col = (tid & 3) << 2;       // 0..12
            *(float4*)&sr[hk][col] = *(const float4*)&g_drt[(b * HH + h0 + hk) * LL + j0 + col];
        }
        if (tid < 32) su[tid] = U[h0 + tid];
        __syncthreads();

#pragma unroll
        for (int hk = 0; hk < 32; hk++) {
            float dl[2];
            *(float2*)dl = *(const float2*)&sl[hk][ty << 1];
            const float dr = sr[hk][tx];
            const float u  = su[hk];
            acc[0] = fmaf(u, tanh_fast(dl[0] + dr), acc[0]);
            acc[1] = fmaf(u, tanh_fast(dl[1] + dr), acc[1]);
        }
        __syncthreads();
    }

    const float lb = logit_bias[0];

#pragma unroll
    for (int a = 0; a < 2; a++) {
        const int i = i0 + (ty << 1) + a;
        const int j = j0 + tx;
        float x = acc[a] + lb;
        if (i == j) x -= 1e8f;

        const int m = i * (BB * LL) + b * LL + j;   // [L,B,L] flat index

        // mask_scores
        out[NTOT + m] = x;

        // p = sigmoid(x)
        const float p = 1.0f / (1.0f + expf(-x));

        // entropy = p*softplus(-x) + (1-p)*softplus(x)
        const float e  = expf(-fabsf(x));
        const float l1 = log1pf(e);
        const float sp_pos = fmaxf(x, 0.f) + l1;   // softplus(x)
        const float sp_neg = fmaxf(-x, 0.f) + l1;  // softplus(-x)
        out[2 * NTOT + m] = p * sp_neg + (1.0f - p) * sp_pos;

        // bernoulli sample, JAX partitionable threefry (key=42)
        const unsigned bits = threefry_bits_partitionable((unsigned)m);
        const float u01 = __uint_as_float((bits >> 9) | 0x3f800000u) - 1.0f;
        out[m] = (u01 < p) ? 1.0f : 0.0f;
    }
}

// ---------------------------------------------------------------------------
// Launch: software pipeline over batch pairs on two forked streams.
//   sA: GEMM(b,b+1) chunks back-to-back (fma pipe)
//   sB: biaffine(b,b+1) chunks, each gated on its GEMM chunk (MUFU pipe)
// Fork/join with events -> valid graph capture; chunk k+1's GEMM overlaps
// chunk k's biaffine on disjoint execution pipes.
// ---------------------------------------------------------------------------
extern "C" void kernel_launch(void* const* d_in, const int* in_sizes, int n_in,
                              void* d_out, int out_size)
{
    const float* enc  = (const float*)d_in[0];
    const float* Wl   = (const float*)d_in[1];
    const float* Wr   = (const float*)d_in[2];
    const float* U    = (const float*)d_in[3];
    const float* bias = (const float*)d_in[4];
    float* out = (float*)d_out;

    static cudaStream_t sA = nullptr, sB = nullptr;
    static cudaEvent_t  eFork = nullptr, eJoin = nullptr, eG[4];
    if (!sA) {
        cudaStreamCreateWithFlags(&sA, cudaStreamNonBlocking);
        cudaStreamCreateWithFlags(&sB, cudaStreamNonBlocking);
        cudaEventCreateWithFlags(&eFork, cudaEventDisableTiming);
        cudaEventCreateWithFlags(&eJoin, cudaEventDisableTiming);
        for (int s = 0; s < 4; s++)
            cudaEventCreateWithFlags(&eG[s], cudaEventDisableTiming);
    }

    // fork from the call stream
    cudaEventRecord(eFork, 0);
    cudaStreamWaitEvent(sA, eFork, 0);
    cudaStreamWaitEvent(sB, eFork, 0);

    dim3 gg(HH / 64, LL / 64, 2);    // 8 x 4 x 2 = 64 CTAs per chunk
    dim3 gb(LL / 16, LL / 32, 2);    // 16 x 8 x 2 = 256 CTAs per chunk

    for (int s = 0; s < 4; s++) {
        const int b0 = 2 * s;
        dual_gemm_kernel<<<gg, 256, 0, sA>>>(enc, Wl, Wr, b0);
        cudaEventRecord(eG[s], sA);
        cudaStreamWaitEvent(sB, eG[s], 0);
        biaffine_kernel<<<gb, 256, 0, sB>>>(U, bias, out, b0);
    }

    // join back to the call stream
    cudaEventRecord(eJoin, sB);
    cudaStreamWaitEvent(0, eJoin, 0);
}

// round 10
// speedup vs baseline: 1.4690x; 1.4690x over previous
#include <cuda_runtime.h>
#include <cstdint>

#define BB 8
#define LL 256
#define DD 512
#define HH 512
#define NTOT (LL*BB*LL)          // 524288

// Scratch: transposed projections dl_t[b][h][i], dr_t[b][h][i]
__device__ float g_dlt[BB*HH*LL];
__device__ float g_drt[BB*HH*LL];

// ---------------------------------------------------------------------------
// f32x2 packed-math helpers
// ---------------------------------------------------------------------------
typedef unsigned long long u64;

__device__ __forceinline__ u64 pack2(float lo, float hi) {
    u64 r; asm("mov.b64 %0, {%1, %2};" : "=l"(r) : "f"(lo), "f"(hi)); return r;
}
__device__ __forceinline__ void unpack2(u64 v, float& lo, float& hi) {
    asm("mov.b64 {%0, %1}, %2;" : "=f"(lo), "=f"(hi) : "l"(v));
}
__device__ __forceinline__ void ffma2(u64& d, u64 a, u64 b) {
    asm("fma.rn.f32x2 %0, %1, %2, %0;" : "+l"(d) : "l"(a), "l"(b));
}

// ---------------------------------------------------------------------------
// Kernel 1: fused dual GEMM (round-7 math). Batches [b_base, b_base+gridDim.z)
// ---------------------------------------------------------------------------
__global__ __launch_bounds__(256) void dual_gemm_kernel(
    const float* __restrict__ enc,
    const float* __restrict__ Wl,
    const float* __restrict__ Wr,
    int b_base)
{
    const int b  = b_base + blockIdx.z;
    const int h0 = blockIdx.x * 64;
    const int i0 = blockIdx.y * 64;

    __shared__ float se[16][68];   // [k][i] (padded)
    __shared__ float swl[16][64];  // [k][h]
    __shared__ float swr[16][64];

    const int tid = threadIdx.x;
    const int tx  = tid & 15;      // h group (4 h each)
    const int ty  = tid >> 4;      // i group (4 i each)

    u64 accl2[4][2], accr2[4][2];  // [a=i][h-pair]
#pragma unroll
    for (int a = 0; a < 4; a++)
#pragma unroll
        for (int c2 = 0; c2 < 2; c2++) { accl2[a][c2] = 0ull; accr2[a][c2] = 0ull; }

    for (int k0 = 0; k0 < DD; k0 += 16) {
        {
            int kk = tid >> 4;          // 0..15
            int hh = (tid & 15) << 2;   // 0..60
            const float4 vl = *(const float4*)&Wl[(k0 + kk) * HH + h0 + hh];
            const float4 vr = *(const float4*)&Wr[(k0 + kk) * HH + h0 + hh];
            *(float4*)&swl[kk][hh] = vl;
            *(float4*)&swr[kk][hh] = vr;
        }
        {
            int ii = tid >> 2;          // 0..63
            int kk = (tid & 3) << 2;    // 0,4,8,12
            const float4 v = *(const float4*)&enc[(b * LL + i0 + ii) * DD + k0 + kk];
            se[kk + 0][ii] = v.x;
            se[kk + 1][ii] = v.y;
            se[kk + 2][ii] = v.z;
            se[kk + 3][ii] = v.w;
        }
        __syncthreads();

#pragma unroll
        for (int kk = 0; kk < 16; kk++) {
            float ev[4];
            *(float4*)ev = *(const float4*)&se[kk][ty << 2];
            const u64 wl01 = *(const u64*)&swl[kk][tx << 2];
            const u64 wl23 = *(const u64*)&swl[kk][(tx << 2) + 2];
            const u64 wr01 = *(const u64*)&swr[kk][tx << 2];
            const u64 wr23 = *(const u64*)&swr[kk][(tx << 2) + 2];
#pragma unroll
            for (int a = 0; a < 4; a++) {
                const u64 ea = pack2(ev[a], ev[a]);
                ffma2(accl2[a][0], ea, wl01);
                ffma2(accl2[a][1], ea, wl23);
                ffma2(accr2[a][0], ea, wr01);
                ffma2(accr2[a][1], ea, wr23);
            }
        }
        __syncthreads();
    }

#pragma unroll
    for (int c2 = 0; c2 < 2; c2++) {
        float l0[4], l1[4], r0[4], r1[4];
#pragma unroll
        for (int a = 0; a < 4; a++) {
            unpack2(accl2[a][c2], l0[a], l1[a]);
            unpack2(accr2[a][c2], r0[a], r1[a]);
        }
        const int h    = h0 + (tx << 2) + (c2 << 1);
        const int base = (b * HH + h) * LL + i0 + (ty << 2);
        *(float4*)&g_dlt[base]      = make_float4(l0[0], l0[1], l0[2], l0[3]);
        *(float4*)&g_dlt[base + LL] = make_float4(l1[0], l1[1], l1[2], l1[3]);
        *(float4*)&g_drt[base]      = make_float4(r0[0], r0[1], r0[2], r0[3]);
        *(float4*)&g_drt[base + LL] = make_float4(r1[0], r1[1], r1[2], r1[3]);
    }
}

// ---------------------------------------------------------------------------
// Threefry2x32, key (0, 42), partitionable path: counter = (0, m),
// output bits = lane0 ^ lane1.
// ---------------------------------------------------------------------------
__device__ __forceinline__ unsigned threefry_bits_partitionable(unsigned m)
{
    const unsigned k0 = 0u, k1 = 42u;
    const unsigned k2 = 0x1BD11BDAu ^ k0 ^ k1;
    unsigned x0 = 0u + k0;
    unsigned x1 = m  + k1;
#define TF_RND(r) { x0 += x1; x1 = __funnelshift_l(x1, x1, r); x1 ^= x0; }
    TF_RND(13) TF_RND(15) TF_RND(26) TF_RND(6)   x0 += k1; x1 += k2 + 1u;
    TF_RND(17) TF_RND(29) TF_RND(16) TF_RND(24)  x0 += k2; x1 += k0 + 2u;
    TF_RND(13) TF_RND(15) TF_RND(26) TF_RND(6)   x0 += k0; x1 += k1 + 3u;
    TF_RND(17) TF_RND(29) TF_RND(16) TF_RND(24)  x0 += k1; x1 += k2 + 4u;
    TF_RND(13) TF_RND(15) TF_RND(26) TF_RND(6)   x0 += k2; x1 += k0 + 5u;
#undef TF_RND
    return x0 ^ x1;
}

__device__ __forceinline__ float tanh_fast(float x)
{
    float y;
    asm("tanh.approx.f32 %0, %1;" : "=f"(y) : "f"(x));
    return y;
}

// ---------------------------------------------------------------------------
// Kernel 2: biaffine + epilogue (round-7 math). Batches
// [b_base, b_base + gridDim.z). 32i x 16j tile per CTA.
// ---------------------------------------------------------------------------
__global__ __launch_bounds__(256) void biaffine_kernel(
    const float* __restrict__ U,
    const float* __restrict__ logit_bias,
    float* __restrict__ out,
    int b_base)
{
    const int b  = b_base + blockIdx.z;
    const int i0 = blockIdx.y * 32;
    const int j0 = blockIdx.x * 16;

    __shared__ float sl[32][32];   // [h][i]
    __shared__ float sr[32][16];   // [h][j]
    __shared__ float su[32];

    const int tid = threadIdx.x;
    const int tx  = tid & 15;      // j (1 each)
    const int ty  = tid >> 4;      // i group (2 each)

    float acc[2] = {0.f, 0.f};

    for (int h0 = 0; h0 < HH; h0 += 32) {
        {
            int hk  = tid >> 3;             // 0..31
            int col = (tid & 7) << 2;       // 0..28
            *(float4*)&sl[hk][col] = *(const float4*)&g_dlt[(b * HH + h0 + hk) * LL + i0 + col];
        }
        if (tid < 128) {
            int hk  = tid >> 2;             // 0..31
            int col = (tid & 3) << 2;       // 0..12
            *(float4*)&sr[hk][col] = *(const float4*)&g_drt[(b * HH + h0 + hk) * LL + j0 + col];
        }
        if (tid < 32) su[tid] = U[h0 + tid];
        __syncthreads();

#pragma unroll
        for (int hk = 0; hk < 32; hk++) {
            float dl[2];
            *(float2*)dl = *(const float2*)&sl[hk][ty << 1];
            const float dr = sr[hk][tx];
            const float u  = su[hk];
            acc[0] = fmaf(u, tanh_fast(dl[0] + dr), acc[0]);
            acc[1] = fmaf(u, tanh_fast(dl[1] + dr), acc[1]);
        }
        __syncthreads();
    }

    const float lb = logit_bias[0];

#pragma unroll
    for (int a = 0; a < 2; a++) {
        const int i = i0 + (ty << 1) + a;
        const int j = j0 + tx;
        float x = acc[a] + lb;
        if (i == j) x -= 1e8f;

        const int m = i * (BB * LL) + b * LL + j;   // [L,B,L] flat index

        // mask_scores
        out[NTOT + m] = x;

        // p = sigmoid(x)
        const float p = 1.0f / (1.0f + expf(-x));

        // entropy = p*softplus(-x) + (1-p)*softplus(x)
        const float e  = expf(-fabsf(x));
        const float l1 = log1pf(e);
        const float sp_pos = fmaxf(x, 0.f) + l1;   // softplus(x)
        const float sp_neg = fmaxf(-x, 0.f) + l1;  // softplus(-x)
        out[2 * NTOT + m] = p * sp_neg + (1.0f - p) * sp_pos;

        // bernoulli sample, JAX partitionable threefry (key=42)
        const unsigned bits = threefry_bits_partitionable((unsigned)m);
        const float u01 = __uint_as_float((bits >> 9) | 0x3f800000u) - 1.0f;
        out[m] = (u01 < p) ? 1.0f : 0.0f;
    }
}

// ---------------------------------------------------------------------------
// Launch: HALF-granularity software pipeline on two forked streams.
//   sA: G(b0..3)  -> G(b4..7)        (128 CTAs each, ~1 tile/SM, fma pipe)
//   sB: B(b0..3)  -> B(b4..7)        (512 CTAs each, MUFU pipe)
// G(b4..7) overlaps B(b0..3) on disjoint pipes. Half-size chunks keep both
// kernels above their occupancy cliffs (round-9 quarters did not).
// ---------------------------------------------------------------------------
extern "C" void kernel_launch(void* const* d_in, const int* in_sizes, int n_in,
                              void* d_out, int out_size)
{
    const float* enc  = (const float*)d_in[0];
    const float* Wl   = (const float*)d_in[1];
    const float* Wr   = (const float*)d_in[2];
    const float* U    = (const float*)d_in[3];
    const float* bias = (const float*)d_in[4];
    float* out = (float*)d_out;

    static cudaStream_t sA = nullptr, sB = nullptr;
    static cudaEvent_t  eFork = nullptr, eJoin = nullptr, eG[2];
    if (!sA) {
        cudaStreamCreateWithFlags(&sA, cudaStreamNonBlocking);
        cudaStreamCreateWithFlags(&sB, cudaStreamNonBlocking);
        cudaEventCreateWithFlags(&eFork, cudaEventDisableTiming);
        cudaEventCreateWithFlags(&eJoin, cudaEventDisableTiming);
        for (int s = 0; s < 2; s++)
            cudaEventCreateWithFlags(&eG[s], cudaEventDisableTiming);
    }

    // fork from the call stream
    cudaEventRecord(eFork, 0);
    cudaStreamWaitEvent(sA, eFork, 0);
    cudaStreamWaitEvent(sB, eFork, 0);

    dim3 gg(HH / 64, LL / 64, 4);    // 8 x 4 x 4 = 128 CTAs per half
    dim3 gb(LL / 16, LL / 32, 4);    // 16 x 8 x 4 = 512 CTAs per half

    for (int s = 0; s < 2; s++) {
        const int b0 = 4 * s;
        dual_gemm_kernel<<<gg, 256, 0, sA>>>(enc, Wl, Wr, b0);
        cudaEventRecord(eG[s], sA);
        cudaStreamWaitEvent(sB, eG[s], 0);
        biaffine_kernel<<<gb, 256, 0, sB>>>(U, bias, out, b0);
    }

    // join back to the call stream
    cudaEventRecord(eJoin, sB);
    cudaStreamWaitEvent(0, eJoin, 0);
}